// round 16
// baseline (speedup 1.0000x reference)
#include <cuda_runtime.h>
#include <math.h>
#include <stdint.h>

#define D_DIM    4096
#define E_DIM    64
#define TOPK     8
#define TILE_M   64
#define BK       32
#define NCH      (D_DIM / BK)     // 128
#define NTHREADS 256

// smem layout (bytes)
// XT: [2 buf][32 k][64 rows] f32, row4 XOR-kf swizzle    -> 2*8192
// BD: [2 buf][32 k][64 e] f32, eg XOR-kf swizzle         -> 2*8192
// PS: partial sumsq [64 rows][8 slots] f32               -> 2048
// RS: inv norm [64] f32
#define XT_OFF   0
#define XT_BUF   8192
#define BD_OFF   16384
#define BD_BUF   8192
#define PS_OFF   32768
#define RS_OFF   34816
#define SMEM_DYN 35328
// epilogue scratch (64*65*4 = 16640 B) reuses XT (+ start of BD) region

static __device__ __forceinline__ uint32_t smem_u32(const void* p) {
    uint32_t a;
    asm("{ .reg .u64 t; cvta.to.shared.u64 t, %1; cvt.u32.u64 %0, t; }" : "=r"(a) : "l"(p));
    return a;
}

static __device__ __forceinline__ void lds_v2u64(uint32_t addr,
                                                 unsigned long long& a,
                                                 unsigned long long& b) {
    asm volatile("ld.shared.v2.b64 {%0,%1}, [%2];" : "=l"(a), "=l"(b) : "r"(addr));
}

static __device__ __forceinline__ void lds_v4b32(uint32_t addr,
                                                 uint32_t& f0, uint32_t& f1,
                                                 uint32_t& f2, uint32_t& f3) {
    asm volatile("ld.shared.v4.b32 {%0,%1,%2,%3}, [%4];"
                 : "=r"(f0), "=r"(f1), "=r"(f2), "=r"(f3) : "r"(addr));
}

static __device__ __forceinline__ void fma2(unsigned long long& d,
                                            unsigned long long a,
                                            unsigned long long b) {
    asm("fma.rn.f32x2 %0, %1, %2, %0;" : "+l"(d) : "l"(a), "l"(b));
}

static __device__ __forceinline__ unsigned long long dup32(uint32_t u) {
    unsigned long long r;
    asm("mov.b64 %0, {%1, %1};" : "=l"(r) : "r"(u));
    return r;
}

static __device__ __forceinline__ float softplus_f(float v) {
    return fmaxf(v, 0.f) + log1pf(expf(-fabsf(v)));
}

__global__ __launch_bounds__(NTHREADS, 2)
void router_ws6_kernel(const float* __restrict__ x,
                       const float* __restrict__ sig,
                       float* __restrict__ out_w,
                       float* __restrict__ out_i,
                       float* __restrict__ out_res)
{
    extern __shared__ char sm[];
    const uint32_t sb = smem_u32(sm);

    const int tid  = threadIdx.x;
    const int wid  = tid >> 5;
    const int lane = tid & 31;
    const int row0 = blockIdx.x * TILE_M;
    const bool is_prod = (wid >= 4);

    // ===== consumer coords (warps 0..3): thread tile 4 rows x 8 experts =====
    const int rh  = wid & 1;
    const int eh  = wid >> 1;
    const int ey  = lane & 7;
    const int ex  = lane >> 3;
    const int r4  = rh * 8 + ey;        // row4 group, 0..15 (rows r4*4..+3)
    const int e8  = eh * 4 + ex;
    const int eg0 = e8 * 2;
    const int eg1 = e8 * 2 + 1;
    const int e0  = e8 * 8;

    // ===== producer coords (warps 4..7) =====
    const int ptid = tid & 127;
    const int prow = ptid >> 3;         // 0..15
    const int slot = ptid & 7;          // float4 k-slot within chunk

    // acc[p][j]: rows (r4*4+2p, +1) x expert columns per e8-stripe
    unsigned long long acc[2][8];
#pragma unroll
    for (int a = 0; a < 2; a++)
#pragma unroll
        for (int j = 0; j < 8; j++) acc[a][j] = 0ull;

    float ss[4];
#pragma unroll
    for (int i = 0; i < 4; i++) ss[i] = 0.f;

    float4 xv[4], sv[4];

    // ---- prologue: LDG chunk 0, store -> buf 0, LDG chunk 1 ----
    if (is_prod) {
#pragma unroll
        for (int i = 0; i < 4; i++)
            xv[i] = *((const float4*)x +
                      (size_t)(row0 + prow + 16 * i) * (D_DIM / 4) + slot);
#pragma unroll
        for (int j = 0; j < 4; j++)
            sv[j] = *((const float4*)sig +
                      (size_t)(prow + 16 * j) * (D_DIM / 4) + slot);
        {
            float* xt = (float*)(sm + XT_OFF);
#pragma unroll
            for (int i = 0; i < 4; i++) {
                float4 v = xv[i];
                const int row = prow + 16 * i;
                ss[i] = fmaf(v.x, v.x, fmaf(v.y, v.y,
                          fmaf(v.z, v.z, fmaf(v.w, v.w, ss[i]))));
                const int base = ((row >> 2) ^ slot) * 4 + (row & 3);
                xt[(slot * 4 + 0) * 64 + base] = v.x;
                xt[(slot * 4 + 1) * 64 + base] = v.y;
                xt[(slot * 4 + 2) * 64 + base] = v.z;
                xt[(slot * 4 + 3) * 64 + base] = v.w;
            }
            float* bd = (float*)(sm + BD_OFF);
#pragma unroll
            for (int j = 0; j < 4; j++) {
                float4 v = sv[j];
                const int e = prow + 16 * j;
                const int base = ((e >> 2) ^ slot) * 4 + (e & 3);
                bd[(slot * 4 + 0) * 64 + base] = v.x;
                bd[(slot * 4 + 1) * 64 + base] = v.y;
                bd[(slot * 4 + 2) * 64 + base] = v.z;
                bd[(slot * 4 + 3) * 64 + base] = v.w;
            }
        }
#pragma unroll
        for (int i = 0; i < 4; i++)
            xv[i] = *((const float4*)x +
                      (size_t)(row0 + prow + 16 * i) * (D_DIM / 4) + 8 + slot);
#pragma unroll
        for (int j = 0; j < 4; j++)
            sv[j] = *((const float4*)sig +
                      (size_t)(prow + 16 * j) * (D_DIM / 4) + 8 + slot);
    }
    __syncthreads();

    // ---- main loop: producers store chunk kc+1 WHILE consumers compute kc ----
    for (int kc = 0; kc < NCH; kc++) {
        const int buf = kc & 1;

        if (is_prod) {
            if (kc + 1 < NCH) {
                const int nbuf = buf ^ 1;
                float* xt = (float*)(sm + XT_OFF + nbuf * XT_BUF);
#pragma unroll
                for (int i = 0; i < 4; i++) {
                    float4 v = xv[i];
                    const int row = prow + 16 * i;
                    ss[i] = fmaf(v.x, v.x, fmaf(v.y, v.y,
                              fmaf(v.z, v.z, fmaf(v.w, v.w, ss[i]))));
                    const int base = ((row >> 2) ^ slot) * 4 + (row & 3);
                    xt[(slot * 4 + 0) * 64 + base] = v.x;
                    xt[(slot * 4 + 1) * 64 + base] = v.y;
                    xt[(slot * 4 + 2) * 64 + base] = v.z;
                    xt[(slot * 4 + 3) * 64 + base] = v.w;
                }
                float* bd = (float*)(sm + BD_OFF + nbuf * BD_BUF);
#pragma unroll
                for (int j = 0; j < 4; j++) {
                    float4 v = sv[j];
                    const int e = prow + 16 * j;
                    const int base = ((e >> 2) ^ slot) * 4 + (e & 3);
                    bd[(slot * 4 + 0) * 64 + base] = v.x;
                    bd[(slot * 4 + 1) * 64 + base] = v.y;
                    bd[(slot * 4 + 2) * 64 + base] = v.z;
                    bd[(slot * 4 + 3) * 64 + base] = v.w;
                }
                if (kc + 2 < NCH) {
#pragma unroll
                    for (int i = 0; i < 4; i++)
                        xv[i] = *((const float4*)x +
                                  (size_t)(row0 + prow + 16 * i) * (D_DIM / 4) +
                                  (kc + 2) * 8 + slot);
#pragma unroll
                    for (int j = 0; j < 4; j++)
                        sv[j] = *((const float4*)sig +
                                  (size_t)(prow + 16 * j) * (D_DIM / 4) +
                                  (kc + 2) * 8 + slot);
                }
            }
        } else {
            // ---- compute chunk kc: per k, 3 LDS + 8 dup-mov + 16 FMA2 ----
            const uint32_t ab = sb + XT_OFF + buf * XT_BUF;
            const uint32_t bb = sb + BD_OFF + buf * BD_BUF;
#pragma unroll
            for (int kf = 0; kf < 8; kf++) {
                const uint32_t aoo = (uint32_t)((r4 ^ kf) * 16);
                const uint32_t bo0 = (uint32_t)((eg0 ^ kf) * 16);
                const uint32_t bo1 = (uint32_t)((eg1 ^ kf) * 16);
#pragma unroll
                for (int kj = 0; kj < 4; kj++) {
                    const uint32_t k = (uint32_t)(kf * 4 + kj);
                    unsigned long long a01, a23;
                    uint32_t f0, f1, f2, f3, f4, f5, f6, f7;
                    lds_v2u64(ab + k * 256u + aoo, a01, a23);
                    lds_v4b32(bb + k * 256u + bo0, f0, f1, f2, f3);
                    lds_v4b32(bb + k * 256u + bo1, f4, f5, f6, f7);
                    unsigned long long b0 = dup32(f0), b1 = dup32(f1);
                    unsigned long long b2 = dup32(f2), b3 = dup32(f3);
                    unsigned long long b4 = dup32(f4), b5 = dup32(f5);
                    unsigned long long b6 = dup32(f6), b7 = dup32(f7);
                    fma2(acc[0][0], a01, b0); fma2(acc[0][1], a01, b1);
                    fma2(acc[0][2], a01, b2); fma2(acc[0][3], a01, b3);
                    fma2(acc[0][4], a01, b4); fma2(acc[0][5], a01, b5);
                    fma2(acc[0][6], a01, b6); fma2(acc[0][7], a01, b7);
                    fma2(acc[1][0], a23, b0); fma2(acc[1][1], a23, b1);
                    fma2(acc[1][2], a23, b2); fma2(acc[1][3], a23, b3);
                    fma2(acc[1][4], a23, b4); fma2(acc[1][5], a23, b5);
                    fma2(acc[1][6], a23, b6); fma2(acc[1][7], a23, b7);
                }
            }
        }
        __syncthreads();
    }

    // ---- producers publish sumsq partials ----
    float* pss = (float*)(sm + PS_OFF);
    if (is_prod) {
#pragma unroll
        for (int i = 0; i < 4; i++)
            pss[(prow + 16 * i) * 8 + slot] = ss[i];
    }
    __syncthreads();

    // ---- inv norm ----
    float* rowsum = (float*)(sm + RS_OFF);
    if (tid < TILE_M) {
        float s = 0.f;
#pragma unroll
        for (int q = 0; q < 8; q++) s += pss[tid * 8 + q];
        rowsum[tid] = 1.f / fmaxf(sqrtf(s), 1e-12f);
    }
    __syncthreads();

    // ---- consumers: scale, write resonance, stash scaled rows ----
    float* scr = (float*)sm;      // [64][65]
    if (!is_prod) {
#pragma unroll
        for (int p = 0; p < 2; p++) {
            const int lr = r4 * 4 + 2 * p;
            const float s0 = 5.0f * rowsum[lr];
            const float s1 = 5.0f * rowsum[lr + 1];
            float lo[8], hi[8];
#pragma unroll
            for (int j = 0; j < 8; j++) {
                unsigned long long u = acc[p][j];
                lo[j] = __uint_as_float((uint32_t)u) * s0;
                hi[j] = __uint_as_float((uint32_t)(u >> 32)) * s1;
            }
            *(float4*)(out_res + (size_t)(row0 + lr) * E_DIM + e0) =
                make_float4(lo[0], lo[1], lo[2], lo[3]);
            *(float4*)(out_res + (size_t)(row0 + lr) * E_DIM + e0 + 4) =
                make_float4(lo[4], lo[5], lo[6], lo[7]);
            *(float4*)(out_res + (size_t)(row0 + lr + 1) * E_DIM + e0) =
                make_float4(hi[0], hi[1], hi[2], hi[3]);
            *(float4*)(out_res + (size_t)(row0 + lr + 1) * E_DIM + e0 + 4) =
                make_float4(hi[4], hi[5], hi[6], hi[7]);
#pragma unroll
            for (int j = 0; j < 8; j++) {
                scr[lr * 65 + e0 + j]       = lo[j];
                scr[(lr + 1) * 65 + e0 + j] = hi[j];
            }
        }
    }
    __syncthreads();

    // ---- fused top-8 + softplus (threads 0..63, one row each) ----
    if (tid < TILE_M) {
        float vals[64];
#pragma unroll
        for (int c = 0; c < 64; c++) vals[c] = scr[tid * 65 + c];
        float* wp = out_w + (size_t)(row0 + tid) * TOPK;
        float* ip = out_i + (size_t)(row0 + tid) * TOPK;
#pragma unroll
        for (int it = 0; it < TOPK; it++) {
            float best = vals[0];
            int bi = 0;
#pragma unroll
            for (int c = 1; c < 64; c++) {
                if (vals[c] > best) { best = vals[c]; bi = c; }
            }
            vals[bi] = -INFINITY;
            wp[it] = softplus_f(best);
            ip[it] = (float)bi;
        }
    }
}

extern "C" void kernel_launch(void* const* d_in, const int* in_sizes, int n_in,
                              void* d_out, int out_size)
{
    const float* x   = (const float*)d_in[0];
    const float* sig = (const float*)d_in[1];
    const int n_rows = in_sizes[0] / D_DIM;   // 16384

    float* out = (float*)d_out;
    float* out_w   = out;
    float* out_i   = out + (size_t)n_rows * TOPK;
    float* out_res = out + (size_t)n_rows * TOPK * 2;

    cudaFuncSetAttribute(router_ws6_kernel,
                         cudaFuncAttributeMaxDynamicSharedMemorySize, SMEM_DYN);

    router_ws6_kernel<<<n_rows / TILE_M, NTHREADS, SMEM_DYN>>>(
        x, sig, out_w, out_i, out_res);
}

// round 17
// speedup vs baseline: 1.1579x; 1.1579x over previous
#include <cuda_runtime.h>
#include <math.h>
#include <stdint.h>

#define D_DIM    4096
#define E_DIM    64
#define TOPK     8
#define TILE_M   128
#define BK       32
#define NCH      (D_DIM / BK)     // 128
#define NTHREADS 256

// smem layout (bytes)
// XT: [2 buf][32 k][128 rows] f32, row4 XOR-kf swizzle   -> 2*16384
// BD: [2 buf][32 k][64 e] f32, eg XOR-kf swizzle         -> 2*8192
// PS: partial sumsq [128 rows][8 slots] f32              -> 4096
// RS: inv norm [128] f32
#define XT_OFF   0
#define XT_BUF   16384
#define BD_OFF   32768
#define BD_BUF   8192
#define PS_OFF   49152
#define RS_OFF   53248
#define SMEM_DYN 53760
// epilogue scratch (128*65*4 = 33280 B) reuses XT (+ start of BD) region

static __device__ __forceinline__ uint32_t smem_u32(const void* p) {
    uint32_t a;
    asm("{ .reg .u64 t; cvta.to.shared.u64 t, %1; cvt.u32.u64 %0, t; }" : "=r"(a) : "l"(p));
    return a;
}

static __device__ __forceinline__ void lds_v2u64(uint32_t addr,
                                                 unsigned long long& a,
                                                 unsigned long long& b) {
    asm volatile("ld.shared.v2.b64 {%0,%1}, [%2];" : "=l"(a), "=l"(b) : "r"(addr));
}

static __device__ __forceinline__ void lds_v4b32(uint32_t addr,
                                                 uint32_t& f0, uint32_t& f1,
                                                 uint32_t& f2, uint32_t& f3) {
    asm volatile("ld.shared.v4.b32 {%0,%1,%2,%3}, [%4];"
                 : "=r"(f0), "=r"(f1), "=r"(f2), "=r"(f3) : "r"(addr));
}

static __device__ __forceinline__ void fma2(unsigned long long& d,
                                            unsigned long long a,
                                            unsigned long long b) {
    asm("fma.rn.f32x2 %0, %1, %2, %0;" : "+l"(d) : "l"(a), "l"(b));
}

static __device__ __forceinline__ unsigned long long dup32(uint32_t u) {
    unsigned long long r;
    asm("mov.b64 %0, {%1, %1};" : "=l"(r) : "r"(u));
    return r;
}

static __device__ __forceinline__ float softplus_f(float v) {
    return fmaxf(v, 0.f) + log1pf(expf(-fabsf(v)));
}

__global__ __launch_bounds__(NTHREADS, 1)
void router_ws7_kernel(const float* __restrict__ x,
                       const float* __restrict__ sig,
                       float* __restrict__ out_w,
                       float* __restrict__ out_i,
                       float* __restrict__ out_res)
{
    extern __shared__ char sm[];
    const uint32_t sb = smem_u32(sm);

    const int tid  = threadIdx.x;
    const int wid  = tid >> 5;
    const int lane = tid & 31;
    const int row0 = blockIdx.x * TILE_M;
    const bool is_prod = (wid >= 4);

    // ===== consumer coords (warps 0..3): thread tile 8 rows x 8 experts =====
    const int rh  = wid & 1;
    const int eh  = wid >> 1;
    const int ey  = lane & 7;
    const int ex  = lane >> 3;
    const int r4a = rh * 16 + ey;
    const int r4b = r4a + 8;
    const int e8  = eh * 4 + ex;
    const int e0  = e8 * 8;
    const uint32_t r4a16 = (uint32_t)r4a * 16u;
    const uint32_t r4b16 = (uint32_t)r4b * 16u;
    const uint32_t eg016 = (uint32_t)(e8 * 2) * 16u;
    const uint32_t eg116 = (uint32_t)(e8 * 2 + 1) * 16u;

    // ===== producer coords (warps 4..7) =====
    const int ptid = tid & 127;
    const int prow = ptid >> 3;         // 0..15
    const int slot = ptid & 7;          // float4 k-slot within chunk

    unsigned long long acc[4][8];
#pragma unroll
    for (int a = 0; a < 4; a++)
#pragma unroll
        for (int j = 0; j < 8; j++) acc[a][j] = 0ull;

    float ss[8];
#pragma unroll
    for (int i = 0; i < 8; i++) ss[i] = 0.f;

    float4 xv[8], sv[4];

    // ---- prologue: LDG chunk 0, store it to buf 0, LDG chunk 1 ----
    if (is_prod) {
#pragma unroll
        for (int i = 0; i < 8; i++)
            xv[i] = *((const float4*)x +
                      (size_t)(row0 + prow + 16 * i) * (D_DIM / 4) + slot);
#pragma unroll
        for (int j = 0; j < 4; j++)
            sv[j] = *((const float4*)sig +
                      (size_t)(prow + 16 * j) * (D_DIM / 4) + slot);
        {
            float* xt = (float*)(sm + XT_OFF);
#pragma unroll
            for (int i = 0; i < 8; i++) {
                float4 v = xv[i];
                const int row = prow + 16 * i;
                ss[i] = fmaf(v.x, v.x, fmaf(v.y, v.y,
                          fmaf(v.z, v.z, fmaf(v.w, v.w, ss[i]))));
                const int base = ((row >> 2) ^ slot) * 4 + (row & 3);
                xt[(slot * 4 + 0) * 128 + base] = v.x;
                xt[(slot * 4 + 1) * 128 + base] = v.y;
                xt[(slot * 4 + 2) * 128 + base] = v.z;
                xt[(slot * 4 + 3) * 128 + base] = v.w;
            }
            float* bd = (float*)(sm + BD_OFF);
#pragma unroll
            for (int j = 0; j < 4; j++) {
                float4 v = sv[j];
                const int e = prow + 16 * j;
                const int base = ((e >> 2) ^ slot) * 4 + (e & 3);
                bd[(slot * 4 + 0) * 64 + base] = v.x;
                bd[(slot * 4 + 1) * 64 + base] = v.y;
                bd[(slot * 4 + 2) * 64 + base] = v.z;
                bd[(slot * 4 + 3) * 64 + base] = v.w;
            }
        }
#pragma unroll
        for (int i = 0; i < 8; i++)
            xv[i] = *((const float4*)x +
                      (size_t)(row0 + prow + 16 * i) * (D_DIM / 4) + 8 + slot);
#pragma unroll
        for (int j = 0; j < 4; j++)
            sv[j] = *((const float4*)sig +
                      (size_t)(prow + 16 * j) * (D_DIM / 4) + 8 + slot);
    }
    __syncthreads();

    // ---- main loop: producers store chunk kc+1 WHILE consumers compute kc ----
    for (int kc = 0; kc < NCH; kc++) {
        const int buf = kc & 1;

        if (is_prod) {
            if (kc + 1 < NCH) {
                const int nbuf = buf ^ 1;
                float* xt = (float*)(sm + XT_OFF + nbuf * XT_BUF);
#pragma unroll
                for (int i = 0; i < 8; i++) {
                    float4 v = xv[i];
                    const int row = prow + 16 * i;
                    ss[i] = fmaf(v.x, v.x, fmaf(v.y, v.y,
                              fmaf(v.z, v.z, fmaf(v.w, v.w, ss[i]))));
                    const int base = ((row >> 2) ^ slot) * 4 + (row & 3);
                    xt[(slot * 4 + 0) * 128 + base] = v.x;
                    xt[(slot * 4 + 1) * 128 + base] = v.y;
                    xt[(slot * 4 + 2) * 128 + base] = v.z;
                    xt[(slot * 4 + 3) * 128 + base] = v.w;
                }
                float* bd = (float*)(sm + BD_OFF + nbuf * BD_BUF);
#pragma unroll
                for (int j = 0; j < 4; j++) {
                    float4 v = sv[j];
                    const int e = prow + 16 * j;
                    const int base = ((e >> 2) ^ slot) * 4 + (e & 3);
                    bd[(slot * 4 + 0) * 64 + base] = v.x;
                    bd[(slot * 4 + 1) * 64 + base] = v.y;
                    bd[(slot * 4 + 2) * 64 + base] = v.z;
                    bd[(slot * 4 + 3) * 64 + base] = v.w;
                }
                if (kc + 2 < NCH) {
#pragma unroll
                    for (int i = 0; i < 8; i++)
                        xv[i] = *((const float4*)x +
                                  (size_t)(row0 + prow + 16 * i) * (D_DIM / 4) +
                                  (kc + 2) * 8 + slot);
#pragma unroll
                    for (int j = 0; j < 4; j++)
                        sv[j] = *((const float4*)sig +
                                  (size_t)(prow + 16 * j) * (D_DIM / 4) +
                                  (kc + 2) * 8 + slot);
                }
            }
        } else {
            // ---- compute chunk kc: 2-deep software-pipelined k-steps ----
            const uint32_t ab = sb + XT_OFF + buf * XT_BUF;
            const uint32_t bb = sb + BD_OFF + buf * BD_BUF;
            unsigned long long fa[2][4];
            uint32_t fb[2][8];

#define LOADK(kk, s) do {                                                    \
    const uint32_t kf16_ = (uint32_t)((((kk) >> 2) & 7) * 16);               \
    lds_v2u64(ab + (uint32_t)(kk) * 512u + (r4a16 ^ kf16_),                  \
              fa[s][0], fa[s][1]);                                           \
    lds_v2u64(ab + (uint32_t)(kk) * 512u + (r4b16 ^ kf16_),                  \
              fa[s][2], fa[s][3]);                                           \
    lds_v4b32(bb + (uint32_t)(kk) * 256u + (eg016 ^ kf16_),                  \
              fb[s][0], fb[s][1], fb[s][2], fb[s][3]);                       \
    lds_v4b32(bb + (uint32_t)(kk) * 256u + (eg116 ^ kf16_),                  \
              fb[s][4], fb[s][5], fb[s][6], fb[s][7]);                       \
} while (0)

            LOADK(0, 0);
#pragma unroll
            for (int kk = 0; kk < 32; kk++) {
                const int s = kk & 1;
                if (kk < 31) LOADK(kk + 1, s ^ 1);
                unsigned long long b0 = dup32(fb[s][0]), b1 = dup32(fb[s][1]);
                unsigned long long b2 = dup32(fb[s][2]), b3 = dup32(fb[s][3]);
                unsigned long long b4 = dup32(fb[s][4]), b5 = dup32(fb[s][5]);
                unsigned long long b6 = dup32(fb[s][6]), b7 = dup32(fb[s][7]);
                fma2(acc[0][0], fa[s][0], b0); fma2(acc[0][1], fa[s][0], b1);
                fma2(acc[0][2], fa[s][0], b2); fma2(acc[0][3], fa[s][0], b3);
                fma2(acc[0][4], fa[s][0], b4); fma2(acc[0][5], fa[s][0], b5);
                fma2(acc[0][6], fa[s][0], b6); fma2(acc[0][7], fa[s][0], b7);
                fma2(acc[1][0], fa[s][1], b0); fma2(acc[1][1], fa[s][1], b1);
                fma2(acc[1][2], fa[s][1], b2); fma2(acc[1][3], fa[s][1], b3);
                fma2(acc[1][4], fa[s][1], b4); fma2(acc[1][5], fa[s][1], b5);
                fma2(acc[1][6], fa[s][1], b6); fma2(acc[1][7], fa[s][1], b7);
                fma2(acc[2][0], fa[s][2], b0); fma2(acc[2][1], fa[s][2], b1);
                fma2(acc[2][2], fa[s][2], b2); fma2(acc[2][3], fa[s][2], b3);
                fma2(acc[2][4], fa[s][2], b4); fma2(acc[2][5], fa[s][2], b5);
                fma2(acc[2][6], fa[s][2], b6); fma2(acc[2][7], fa[s][2], b7);
                fma2(acc[3][0], fa[s][3], b0); fma2(acc[3][1], fa[s][3], b1);
                fma2(acc[3][2], fa[s][3], b2); fma2(acc[3][3], fa[s][3], b3);
                fma2(acc[3][4], fa[s][3], b4); fma2(acc[3][5], fa[s][3], b5);
                fma2(acc[3][6], fa[s][3], b6); fma2(acc[3][7], fa[s][3], b7);
            }
#undef LOADK
        }
        __syncthreads();
    }

    // ---- producers publish sumsq partials ----
    float* pss = (float*)(sm + PS_OFF);
    if (is_prod) {
#pragma unroll
        for (int i = 0; i < 8; i++)
            pss[(prow + 16 * i) * 8 + slot] = ss[i];
    }
    __syncthreads();

    // ---- inv norm ----
    float* rowsum = (float*)(sm + RS_OFF);
    if (tid < TILE_M) {
        float s = 0.f;
#pragma unroll
        for (int q = 0; q < 8; q++) s += pss[tid * 8 + q];
        rowsum[tid] = 1.f / fmaxf(sqrtf(s), 1e-12f);
    }
    __syncthreads();

    // ---- consumers: scale, write resonance, stash scaled rows ----
    float* scr = (float*)sm;      // [128][65]
    if (!is_prod) {
#pragma unroll
        for (int g = 0; g < 2; g++) {
            const int r4 = g ? r4b : r4a;
#pragma unroll
            for (int p = 0; p < 2; p++) {
                const int lr = r4 * 4 + 2 * p;
                const float s0 = 5.0f * rowsum[lr];
                const float s1 = 5.0f * rowsum[lr + 1];
                float lo[8], hi[8];
#pragma unroll
                for (int j = 0; j < 8; j++) {
                    unsigned long long u = acc[g * 2 + p][j];
                    lo[j] = __uint_as_float((uint32_t)u) * s0;
                    hi[j] = __uint_as_float((uint32_t)(u >> 32)) * s1;
                }
                *(float4*)(out_res + (size_t)(row0 + lr) * E_DIM + e0) =
                    make_float4(lo[0], lo[1], lo[2], lo[3]);
                *(float4*)(out_res + (size_t)(row0 + lr) * E_DIM + e0 + 4) =
                    make_float4(lo[4], lo[5], lo[6], lo[7]);
                *(float4*)(out_res + (size_t)(row0 + lr + 1) * E_DIM + e0) =
                    make_float4(hi[0], hi[1], hi[2], hi[3]);
                *(float4*)(out_res + (size_t)(row0 + lr + 1) * E_DIM + e0 + 4) =
                    make_float4(hi[4], hi[5], hi[6], hi[7]);
#pragma unroll
                for (int j = 0; j < 8; j++) {
                    scr[lr * 65 + e0 + j]       = lo[j];
                    scr[(lr + 1) * 65 + e0 + j] = hi[j];
                }
            }
        }
    }
    __syncthreads();

    // ---- fused top-8 + softplus (threads 0..127, one row each) ----
    if (tid < TILE_M) {
        float vals[64];
#pragma unroll
        for (int c = 0; c < 64; c++) vals[c] = scr[tid * 65 + c];
        float* wp = out_w + (size_t)(row0 + tid) * TOPK;
        float* ip = out_i + (size_t)(row0 + tid) * TOPK;
#pragma unroll
        for (int it = 0; it < TOPK; it++) {
            float best = vals[0];
            int bi = 0;
#pragma unroll
            for (int c = 1; c < 64; c++) {
                if (vals[c] > best) { best = vals[c]; bi = c; }
            }
            vals[bi] = -INFINITY;
            wp[it] = softplus_f(best);
            ip[it] = (float)bi;
        }
    }
}

extern "C" void kernel_launch(void* const* d_in, const int* in_sizes, int n_in,
                              void* d_out, int out_size)
{
    const float* x   = (const float*)d_in[0];
    const float* sig = (const float*)d_in[1];
    const int n_rows = in_sizes[0] / D_DIM;   // 16384

    float* out = (float*)d_out;
    float* out_w   = out;
    float* out_i   = out + (size_t)n_rows * TOPK;
    float* out_res = out + (size_t)n_rows * TOPK * 2;

    cudaFuncSetAttribute(router_ws7_kernel,
                         cudaFuncAttributeMaxDynamicSharedMemorySize, SMEM_DYN);

    router_ws7_kernel<<<n_rows / TILE_M, NTHREADS, SMEM_DYN>>>(
        x, sig, out_w, out_i, out_res);
}